// round 3
// baseline (speedup 1.0000x reference)
#include <cuda_runtime.h>
#include <stdint.h>

#define N 384
#define NN (N * N)

// ---------------- scratch (no allocations allowed) ----------------
__device__ float g_norms[8 * N];      // [layer*2 + side][row]
__device__ float g_cost[5 * NN];      // 4 layer costs + combined
__device__ int   g_rowcol[5 * N];     // row -> matched col, per solve

// ---------------- row squared-norms (both sides of one layer) ----------------
__global__ void norms_kernel(const float* __restrict__ src, int d, int layer) {
    int side = blockIdx.x >> 8 >= 0 ? (blockIdx.x / N) : 0;   // 0 or 1
    int row  = blockIdx.x - side * N;
    const float* p = src + ((size_t)side * N + row) * d;
    int t = threadIdx.x;
    float hi = 0.f, lo = 0.f;
    int c = 0;
    for (int k = t; k < d; k += 128, c++) {
        float x = p[k];
        lo += x * x;
        if ((c & 63) == 63) { hi += lo; lo = 0.f; }
    }
    hi += lo;
    __shared__ float s[4];
    #pragma unroll
    for (int off = 16; off; off >>= 1) hi += __shfl_down_sync(0xffffffffu, hi, off);
    if ((t & 31) == 0) s[t >> 5] = hi;
    __syncthreads();
    if (t == 0) g_norms[(2 * layer + side) * N + row] = (s[0] + s[1]) + (s[2] + s[3]);
}

// ---------------- cost GEMM: cost[r][c] = clip(ra[r] - 2 A_r.B_c + rb[c], 0)/d ----------------
#define TS 64
#define KT 16
__global__ void __launch_bounds__(256) gemm_cost_kernel(
    const float* __restrict__ A, const float* __restrict__ B,
    int d, float invd, int layer)
{
    __shared__ float As[KT][TS + 4];
    __shared__ float Bs[KT][TS + 4];
    const float* ra = &g_norms[(2 * layer) * N];
    const float* rb = &g_norms[(2 * layer + 1) * N];
    float* cost = &g_cost[layer * NN];

    int tid = threadIdx.x;
    int tx = tid & 15, ty = tid >> 4;
    int row0 = blockIdx.y * TS, col0 = blockIdx.x * TS;
    int lr = tid >> 2, lk = (tid & 3) * 4;

    float acc[4][4], hi[4][4];
    #pragma unroll
    for (int i = 0; i < 4; i++)
        #pragma unroll
        for (int j = 0; j < 4; j++) { acc[i][j] = 0.f; hi[i][j] = 0.f; }

    int nt = d / KT;
    for (int it = 0; it < nt; it++) {
        int k0 = it * KT;
        float4 a = *(const float4*)(A + (size_t)(row0 + lr) * d + k0 + lk);
        float4 b = *(const float4*)(B + (size_t)(col0 + lr) * d + k0 + lk);
        __syncthreads();
        As[lk + 0][lr] = a.x; As[lk + 1][lr] = a.y; As[lk + 2][lr] = a.z; As[lk + 3][lr] = a.w;
        Bs[lk + 0][lr] = b.x; Bs[lk + 1][lr] = b.y; Bs[lk + 2][lr] = b.z; Bs[lk + 3][lr] = b.w;
        __syncthreads();
        #pragma unroll
        for (int kk = 0; kk < KT; kk++) {
            float4 av = *(const float4*)&As[kk][ty * 4];
            float4 bv = *(const float4*)&Bs[kk][tx * 4];
            float aa[4] = {av.x, av.y, av.z, av.w};
            float bb[4] = {bv.x, bv.y, bv.z, bv.w};
            #pragma unroll
            for (int i = 0; i < 4; i++)
                #pragma unroll
                for (int j = 0; j < 4; j++)
                    acc[i][j] += aa[i] * bb[j];
        }
        // two-level accumulation: fold every 256 K for accuracy
        if ((it & 15) == 15) {
            #pragma unroll
            for (int i = 0; i < 4; i++)
                #pragma unroll
                for (int j = 0; j < 4; j++) { hi[i][j] += acc[i][j]; acc[i][j] = 0.f; }
        }
    }
    #pragma unroll
    for (int i = 0; i < 4; i++)
        #pragma unroll
        for (int j = 0; j < 4; j++) hi[i][j] += acc[i][j];

    #pragma unroll
    for (int i = 0; i < 4; i++) {
        int r = row0 + ty * 4 + i;
        float rav = ra[r];
        #pragma unroll
        for (int j = 0; j < 4; j++) {
            int c = col0 + tx * 4 + j;
            float sq = (rav - 2.0f * hi[i][j]) + rb[c];
            cost[r * N + c] = fmaxf(sq, 0.0f) * invd;
        }
    }
}

// ---------------- combined = (((c0 + 0.5 c1) + 0.25 c2) + 0.125 c3), ref fp32 order ----------------
__global__ void combine_kernel() {
    int idx = blockIdx.x * blockDim.x + threadIdx.x;
    if (idx < NN) {
        float c = g_cost[idx];
        c = c + 0.5f   * g_cost[NN + idx];
        c = c + 0.25f  * g_cost[2 * NN + idx];
        c = c + 0.125f * g_cost[3 * NN + idx];
        g_cost[4 * NN + idx] = c;
    }
}

// ---------------- LAP (Jonker-Volgenant, Dijkstra form, fp64) : one block per matrix ----------------
__global__ void __launch_bounds__(N) lap_kernel() {
    int m = blockIdx.x;
    const float* __restrict__ C = &g_cost[m * NN];

    __shared__ double u[N], v[N];
    __shared__ int matchRow[N];   // col -> row
    __shared__ int way[N];        // parent col on shortest path (-1 = start row)
    __shared__ double rwval[12];
    __shared__ int rwidx[12];
    __shared__ double s_mind;
    __shared__ int s_j1, s_i0;

    int j = threadIdx.x;
    u[j] = 0.0; v[j] = 0.0; matchRow[j] = -1;
    __syncthreads();

    for (int i = 0; i < N; i++) {
        double D = (double)C[i * N + j] - u[i] - v[j];
        way[j] = -1;
        bool vis = false;
        int sink = -1;
        double mind = 0.0;
        __syncthreads();

        // Hard bound N+1: each pass either finds a free column (break) or marks
        // a previously-unvisited column; guarantees termination even if costs
        // were pathological (defense against hang -> harness timeout).
        for (int iter = 0; iter <= N; iter++) {
            // block argmin over unvisited (tie-break: lowest index, matches np.argmin)
            double val = vis ? 1e300 : D;
            int idx = j;
            #pragma unroll
            for (int off = 16; off; off >>= 1) {
                double ov = __shfl_down_sync(0xffffffffu, val, off);
                int oi = __shfl_down_sync(0xffffffffu, idx, off);
                if (ov < val || (ov == val && oi < idx)) { val = ov; idx = oi; }
            }
            if ((j & 31) == 0) { rwval[j >> 5] = val; rwidx[j >> 5] = idx; }
            __syncthreads();
            if (j == 0) {
                double bv = rwval[0]; int bi = rwidx[0];
                #pragma unroll
                for (int t = 1; t < 12; t++) {
                    double tv = rwval[t]; int ti = rwidx[t];
                    if (tv < bv || (tv == bv && ti < bi)) { bv = tv; bi = ti; }
                }
                s_mind = bv; s_j1 = bi; s_i0 = matchRow[bi];
            }
            __syncthreads();
            int j1 = s_j1, i0 = s_i0;
            mind = s_mind;
            if (i0 < 0) { sink = j1; break; }       // free column found
            if (j == j1) vis = true;
            if (!vis) {                              // relax via row i0 (matched to j1)
                double cand = mind + (double)C[(size_t)i0 * N + j] - u[i0] - v[j];
                if (cand < D) { D = cand; way[j] = j1; }
            }
            // no extra barrier needed: D/vis/way[j] are thread-private or own-slot
            // writes; the next iteration's barriers order rwval/s_* reuse.
        }

        // dual updates (sink excluded from visited set)
        if (vis) {
            double dd = mind - D;
            v[j] -= dd;
            u[matchRow[j]] += dd;   // distinct rows per visited col: no conflict
        }
        if (j == 0) u[i] += mind;
        __syncthreads();

        // augment along parent chain (serial, thread 0)
        if (j == 0 && sink >= 0) {
            int jj = sink;
            while (true) {
                int pj = way[jj];
                if (pj < 0) { matchRow[jj] = i; break; }
                matchRow[jj] = matchRow[pj];
                jj = pj;
            }
        }
        __syncthreads();
    }

    g_rowcol[m * N + matchRow[j]] = j;   // row -> col
}

// ---------------- finalize: hamming total + outputs ----------------
__global__ void finalize_kernel(const long long* __restrict__ ipA,
                                const long long* __restrict__ ipB,
                                float* __restrict__ out, int out_size)
{
    __shared__ int idealcol[N];
    __shared__ int cnt[4];
    __shared__ float s_total;
    int t = threadIdx.x;
    if (t < 4) cnt[t] = 0;
    __syncthreads();
    idealcol[(int)ipA[t]] = (int)ipB[t];
    __syncthreads();
    #pragma unroll
    for (int l = 0; l < 4; l++)
        if (g_rowcol[l * N + t] == idealcol[t]) atomicAdd(&cnt[l], 1);
    __syncthreads();
    if (t == 0) {
        const double w[4] = {1.0, 0.5, 0.25, 0.125};
        double tot = 0.0;
        for (int l = 0; l < 4; l++)
            tot += w[l] * ((double)(2 * N - 2 * cnt[l]) / (double)N);
        s_total = (float)tot;
    }
    __syncthreads();
    float total = s_total;
    int colind = g_rowcol[4 * N + t];

    if (out_size >= 2 * N + 1) {
        if (t == 0) out[0] = total;
        out[1 + t] = (float)t;
        out[1 + N + t] = (float)colind;
        for (int idx = 2 * N + 1 + t; idx < out_size; idx += N) out[idx] = 0.0f;
    } else if (out_size == 2 * N) {
        out[t] = (float)t;
        out[N + t] = (float)colind;
    } else if (out_size >= 1) {
        if (t == 0) out[0] = total;
        for (int idx = 1 + t; idx < out_size; idx += N) out[idx] = 0.0f;
    }
}

// ---------------- launch ----------------
extern "C" void kernel_launch(void* const* d_in, const int* in_sizes, int n_in,
                              void* d_out, int out_size)
{
    const float* lat[4];
    int dims[4];
    for (int l = 0; l < 4; l++) {
        lat[l] = (const float*)d_in[l];
        dims[l] = in_sizes[l] / (2 * N);
    }
    const long long* ipA = (const long long*)d_in[4];
    const long long* ipB = (const long long*)d_in[5];

    for (int l = 0; l < 4; l++)
        norms_kernel<<<2 * N, 128>>>(lat[l], dims[l], l);
    for (int l = 0; l < 4; l++)
        gemm_cost_kernel<<<dim3(6, 6), 256>>>(
            lat[l], lat[l] + (size_t)N * dims[l], dims[l], 1.0f / (float)dims[l], l);
    combine_kernel<<<(NN + 255) / 256, 256>>>();
    lap_kernel<<<5, N>>>();
    finalize_kernel<<<1, N>>>(ipA, ipB, (float*)d_out, out_size);
}